// round 1
// baseline (speedup 1.0000x reference)
#include <cuda_runtime.h>
#include <math.h>

// ---------------------------------------------------------------------------
// DeepseekV4LearnedRouter
//   hidden [N=16384, D=4096] f32, weight [E=256, D=4096] f32, bias [E] f32
//   logits = hidden @ weight^T
//   scores = sqrt(softplus(logits)); top-8 on scores+bias; renorm * 2.5
//   out: probs [N,E] f32  ||  routing_map [N,E] as 0.0/1.0 f32
// ---------------------------------------------------------------------------

#define BM 128
#define BN 128
#define BK 32
#define PAD 4

#define MAX_N 16384
#define MAX_E 256

// scratch logits (no cudaMalloc allowed)
__device__ float g_logits[(size_t)MAX_N * MAX_E];

__global__ __launch_bounds__(256, 2)
void router_gemm_kernel(const float* __restrict__ A,   // [N, K] hidden
                        const float* __restrict__ W,   // [E, K] weight
                        float* __restrict__ C,         // [N, E] logits
                        int N, int E, int K)
{
    __shared__ float As[BK][BM + PAD];
    __shared__ float Bs[BK][BN + PAD];

    const int bm = blockIdx.x * BM;
    const int bn = blockIdx.y * BN;
    const int tid = threadIdx.x;
    const int tx = tid & 15;          // 0..15
    const int ty = tid >> 4;          // 0..15
    const int tm0 = ty * 8;
    const int tn0 = tx * 8;

    // global-load mapping: each thread loads float4s; row = tid/8, k4 = (tid%8)*4
    const int lrow = tid >> 3;        // 0..31
    const int lk   = (tid & 7) * 4;   // 0..28

    const float* Aptr = A + (size_t)bm * K;
    const float* Wptr = W + (size_t)bn * K;

    float acc[8][8];
#pragma unroll
    for (int i = 0; i < 8; i++)
#pragma unroll
        for (int j = 0; j < 8; j++)
            acc[i][j] = 0.0f;

    for (int k0 = 0; k0 < K; k0 += BK) {
        // ---- load A tile [BM x BK] transposed into As[k][m] ----
#pragma unroll
        for (int r = 0; r < BM; r += 32) {
            float4 v = *(const float4*)(Aptr + (size_t)(lrow + r) * K + (k0 + lk));
            As[lk + 0][lrow + r] = v.x;
            As[lk + 1][lrow + r] = v.y;
            As[lk + 2][lrow + r] = v.z;
            As[lk + 3][lrow + r] = v.w;
        }
        // ---- load W tile [BN x BK] transposed into Bs[k][n] ----
#pragma unroll
        for (int r = 0; r < BN; r += 32) {
            float4 v = *(const float4*)(Wptr + (size_t)(lrow + r) * K + (k0 + lk));
            Bs[lk + 0][lrow + r] = v.x;
            Bs[lk + 1][lrow + r] = v.y;
            Bs[lk + 2][lrow + r] = v.z;
            Bs[lk + 3][lrow + r] = v.w;
        }
        __syncthreads();

#pragma unroll
        for (int k = 0; k < BK; k++) {
            float a[8], b[8];
            *(float4*)&a[0] = *(const float4*)&As[k][tm0];
            *(float4*)&a[4] = *(const float4*)&As[k][tm0 + 4];
            *(float4*)&b[0] = *(const float4*)&Bs[k][tn0];
            *(float4*)&b[4] = *(const float4*)&Bs[k][tn0 + 4];
#pragma unroll
            for (int i = 0; i < 8; i++)
#pragma unroll
                for (int j = 0; j < 8; j++)
                    acc[i][j] = fmaf(a[i], b[j], acc[i][j]);
        }
        __syncthreads();
    }

    // ---- store C tile ----
#pragma unroll
    for (int i = 0; i < 8; i++) {
        const int row = bm + tm0 + i;
        float4* cp = (float4*)(C + (size_t)row * E + bn + tn0);
        cp[0] = make_float4(acc[i][0], acc[i][1], acc[i][2], acc[i][3]);
        cp[1] = make_float4(acc[i][4], acc[i][5], acc[i][6], acc[i][7]);
    }
}

// one warp per token: 256 experts = 8 per lane (expert e = j*32 + lane)
__global__ __launch_bounds__(256)
void router_topk_kernel(const float* __restrict__ logits,  // [N, 256]
                        const float* __restrict__ bias,    // [256]
                        float* __restrict__ probs,         // [N, 256]
                        float* __restrict__ rmap,          // [N, 256]
                        int N)
{
    const int warp = (blockIdx.x * blockDim.x + threadIdx.x) >> 5;
    const int lane = threadIdx.x & 31;
    if (warp >= N) return;

    const float* lrow = logits + (size_t)warp * 256;

    float score[8];   // unbiased sqrt-softplus score
    float selsc[8];   // selection score (biased); set -inf once picked
    bool  sel[8];

#pragma unroll
    for (int j = 0; j < 8; j++) {
        const int e = j * 32 + lane;
        const float x = lrow[e];
        // softplus(x) = max(x,0) + log1p(exp(-|x|))
        const float sp = fmaxf(x, 0.0f) + log1pf(expf(-fabsf(x)));
        const float s = sqrtf(sp);
        score[j] = s;
        selsc[j] = s + bias[e];
        sel[j] = false;
    }

    float sumw = 0.0f;

#pragma unroll
    for (int it = 0; it < 8; it++) {
        // local argmax among this lane's 8 slots (lowest j wins ties -> lowest e)
        float bestv = -INFINITY;
        int bestj = -1;
#pragma unroll
        for (int j = 0; j < 8; j++) {
            if (selsc[j] > bestv) { bestv = selsc[j]; bestj = j; }
        }
        int beste = (bestj >= 0) ? (bestj * 32 + lane) : 0x7fffffff;

        // warp argmax: higher value wins; tie -> lower expert index (jax top_k)
#pragma unroll
        for (int off = 16; off > 0; off >>= 1) {
            const float ov = __shfl_xor_sync(0xffffffffu, bestv, off);
            const int   oe = __shfl_xor_sync(0xffffffffu, beste, off);
            if (ov > bestv || (ov == bestv && oe < beste)) {
                bestv = ov;
                beste = oe;
            }
        }

        // winning lane marks selection
        if ((beste & 31) == lane) {
            const int j = beste >> 5;
            sel[j] = true;
            selsc[j] = -INFINITY;
            sumw += score[j];
        }
    }

    // total of selected unbiased scores
    float tot = sumw;
#pragma unroll
    for (int off = 16; off > 0; off >>= 1)
        tot += __shfl_xor_sync(0xffffffffu, tot, off);

    const float scale = 2.5f / fmaxf(tot, 1e-12f);

#pragma unroll
    for (int j = 0; j < 8; j++) {
        const int e = j * 32 + lane;
        const size_t o = (size_t)warp * 256 + e;
        probs[o] = sel[j] ? score[j] * scale : 0.0f;
        rmap[o]  = sel[j] ? 1.0f : 0.0f;
    }
}

extern "C" void kernel_launch(void* const* d_in, const int* in_sizes, int n_in,
                              void* d_out, int out_size)
{
    const float* hidden = (const float*)d_in[0];
    const float* weight = (const float*)d_in[1];
    const float* bias   = (const float*)d_in[2];

    const int E = in_sizes[2];                 // 256
    const int D = in_sizes[1] / E;             // 4096
    const int N = in_sizes[0] / D;             // 16384

    float* out = (float*)d_out;
    float* probs = out;                        // [N, E]
    float* rmap  = out + (size_t)N * E;        // [N, E] as 0.0/1.0

    float* logits = nullptr;
    cudaGetSymbolAddress((void**)&logits, g_logits);

    dim3 ggrid((N + BM - 1) / BM, (E + BN - 1) / BN);
    router_gemm_kernel<<<ggrid, 256>>>(hidden, weight, logits, N, E, D);

    const int warps_per_block = 8;             // 256 threads
    const int tblocks = (N + warps_per_block - 1) / warps_per_block;
    router_topk_kernel<<<tblocks, 256>>>(logits, bias, probs, rmap, N);

    (void)n_in; (void)out_size;
}